// round 10
// baseline (speedup 1.0000x reference)
#include <cuda_runtime.h>

#define NN 10000
#define NE 320000
#define HID 128
#define SME_FLOATS 27520
#define SMN_FLOATS 25024

__device__ float g_hA[NN * HID];
__device__ float g_hB[NN * HID];
__device__ float g_x[NN * 3];
__device__ float g_vel[NN * 3];
__device__ float g_aggx[NN * 3];
__device__ float g_aggh[NN * HID];
__device__ float g_cnt[NN];

__device__ __forceinline__ float siluf(float v) {
    return v * __fdividef(1.f, 1.f + __expf(-v));
}
__device__ __forceinline__ float sigf(float v) {
    return __fdividef(1.f, 1.f + __expf(-v));
}

__device__ __forceinline__ unsigned long long pack2(float v) {
    unsigned long long r;
    asm("mov.b64 %0, {%1, %1};" : "=l"(r) : "f"(v));
    return r;
}
__device__ __forceinline__ void unpack2(unsigned long long p, float& a, float& b) {
    asm("mov.b64 {%0, %1}, %2;" : "=f"(a), "=f"(b) : "l"(p));
}
__device__ __forceinline__ void ffma2(unsigned long long& d, unsigned long long a,
                                      unsigned long long b) {
    asm("fma.rn.f32x2 %0, %1, %2, %0;" : "+l"(d) : "l"(a), "l"(b));
}
__device__ __forceinline__ void red4(float* p, float a, float b, float c, float d) {
    asm volatile("red.global.add.v4.f32 [%0], {%1, %2, %3, %4};"
                 :: "l"(p), "f"(a), "f"(b), "f"(c), "f"(d) : "memory");
}

// XOR swizzle: A[k][e] stored at sA[k*64 + (e ^ (4*((k>>2)&15)))].
// 2D warp tiling over a 64-edge x 128-col tile, 256 threads:
//   warp w: col group wc=w&3 (cols 32wc..+31), edge group we=w>>2 (edges 32we..+31)
//   thread: cols C0=32wc+4*(tx&7)..+3, edges E0=32we+8*(tx>>3)..+7
// Per k: W read = 1 wavefront (128B block), A = 2 wavefronts (XOR preserves
// aligned 32-float blocks). acc[e][j] = (edge E0+e, col C0+j).
__device__ __forceinline__ void gemm64(const float* sA, float* sW,
                                       const float* __restrict__ gW,
                                       int K, int Kpad, float acc[8][4]) {
    const int tid = threadIdx.x, tx = tid & 31, w = tid >> 5;
    const int E0 = ((w >> 2) << 5) + ((tx >> 3) << 3);
    const int C0 = ((w & 3) << 5) + ((tx & 7) << 2);
    unsigned long long a2[4][4];
#pragma unroll
    for (int p = 0; p < 4; p++)
#pragma unroll
        for (int j = 0; j < 4; j++) a2[p][j] = 0ULL;
    const float4* __restrict__ gW4 = (const float4*)gW;
    const int nch = Kpad >> 5;
    float4 r[4];
#pragma unroll
    for (int i = 0; i < 4; i++) {
        int f = tid + i * 256;
        int rr = f >> 5;
        r[i] = (rr < K) ? gW4[rr * 32 + (f & 31)] : make_float4(0.f, 0.f, 0.f, 0.f);
    }
#pragma unroll
    for (int i = 0; i < 4; i++) ((float4*)sW)[tid + i * 256] = r[i];
    for (int ci = 0; ci < nch; ci++) {
        __syncthreads();
        const int kb = ci << 5;
        const float* buf = sW + ((ci & 1) << 12);
        const bool more = (ci + 1 < nch);
        if (more) {
#pragma unroll
            for (int i = 0; i < 4; i++) {
                int f = tid + i * 256;
                int rr = kb + 32 + (f >> 5);
                r[i] = (rr < K) ? gW4[rr * 32 + (f & 31)]
                                : make_float4(0.f, 0.f, 0.f, 0.f);
            }
        }
#pragma unroll 8
        for (int kk = 0; kk < 32; kk++) {
            int k = kb + kk;
            int xv = ((k >> 2) & 15) << 2;
            const float* ar = sA + k * 64;
            ulonglong2 q0 = *(const ulonglong2*)(ar + (E0 ^ xv));        // edges E0..+3
            ulonglong2 q1 = *(const ulonglong2*)(ar + ((E0 + 4) ^ xv));  // edges E0+4..+7
            float4 wv = *(const float4*)(buf + kk * 128 + C0);
            unsigned long long w0 = pack2(wv.x), w1 = pack2(wv.y);
            unsigned long long w2 = pack2(wv.z), w3 = pack2(wv.w);
            ffma2(a2[0][0], q0.x, w0); ffma2(a2[0][1], q0.x, w1);
            ffma2(a2[0][2], q0.x, w2); ffma2(a2[0][3], q0.x, w3);
            ffma2(a2[1][0], q0.y, w0); ffma2(a2[1][1], q0.y, w1);
            ffma2(a2[1][2], q0.y, w2); ffma2(a2[1][3], q0.y, w3);
            ffma2(a2[2][0], q1.x, w0); ffma2(a2[2][1], q1.x, w1);
            ffma2(a2[2][2], q1.x, w2); ffma2(a2[2][3], q1.x, w3);
            ffma2(a2[3][0], q1.y, w0); ffma2(a2[3][1], q1.y, w1);
            ffma2(a2[3][2], q1.y, w2); ffma2(a2[3][3], q1.y, w3);
        }
        if (more) {
            float* nb = sW + (((ci + 1) & 1) << 12);
#pragma unroll
            for (int i = 0; i < 4; i++) ((float4*)nb)[tid + i * 256] = r[i];
        }
    }
#pragma unroll
    for (int p = 0; p < 4; p++)
#pragma unroll
        for (int j = 0; j < 4; j++) unpack2(a2[p][j], acc[2 * p][j], acc[2 * p + 1][j]);
    __syncthreads();
}

// Write acc (+bias, silu) transposed into sA rows baseRow..baseRow+127 (XOR swizzle).
__device__ __forceinline__ void store_out64(float* sA, int baseRow, float acc[8][4],
                                            const float* __restrict__ bias) {
    const int tid = threadIdx.x, tx = tid & 31, w = tid >> 5;
    const int E0 = ((w >> 2) << 5) + ((tx >> 3) << 3);
    const int C0 = ((w & 3) << 5) + ((tx & 7) << 2);
#pragma unroll
    for (int j = 0; j < 4; j++) {
        int c = C0 + j;
        float b = bias[c];
        int xvr = ((c >> 2) & 15) << 2;
        float* rp = sA + (baseRow + c) * 64;
        *(float4*)(rp + (E0 ^ xvr)) = make_float4(
            siluf(acc[0][j] + b), siluf(acc[1][j] + b),
            siluf(acc[2][j] + b), siluf(acc[3][j] + b));
        *(float4*)(rp + ((E0 + 4) ^ xvr)) = make_float4(
            siluf(acc[4][j] + b), siluf(acc[5][j] + b),
            siluf(acc[6][j] + b), siluf(acc[7][j] + b));
    }
}

__global__ void k_setup(const float* __restrict__ h_in, const float* __restrict__ x_in,
                        const float* __restrict__ vel_in, const float* __restrict__ emb_w,
                        const float* __restrict__ emb_b) {
    int i = blockIdx.x * blockDim.x + threadIdx.x;
    if (i < NN * 3) { g_x[i] = x_in[i]; g_vel[i] = vel_in[i]; }
    if (i < NN) g_cnt[i] = 0.f;
    if (i < NN * HID) {
        int n = i >> 7, c = i & 127;
        float s = emb_b[c];
#pragma unroll
        for (int k = 0; k < 6; k++) s += h_in[n * 6 + k] * emb_w[k * HID + c];
        g_hA[i] = s;
    }
}

__global__ void k_count(const int* __restrict__ edges) {
    int e = blockIdx.x * blockDim.x + threadIdx.x;
    if (e < NE) atomicAdd(&g_cnt[edges[e]], 1.f);
}

__global__ void k_zero() {
    int i = blockIdx.x * blockDim.x + threadIdx.x;
    if (i < NN * 3) g_aggx[i] = 0.f;
    if (i < NN * HID) g_aggh[i] = 0.f;
}

__global__ void __launch_bounds__(256, 2) k_edge(
    int cur, const float* __restrict__ ea, const int* __restrict__ edges,
    const float* __restrict__ ew1, const float* __restrict__ eb1,
    const float* __restrict__ ew2, const float* __restrict__ eb2,
    const float* __restrict__ aw, const float* __restrict__ ab,
    const float* __restrict__ cw1, const float* __restrict__ cb1,
    const float* __restrict__ cw2) {
    extern __shared__ float sm[];
    float* sA = sm;                    // 288 rows x 64
    float* sW = sm + 18432;            // 2 x 4096 (double buffer)
    float* sCD = sm + 26624;           // 192
    float* sWv = sm + 26816;           // 64
    float* sAw = sm + 26880;           // 128
    float* sCw2 = sm + 27008;          // 128
    float* sGp = sm + 27136;           // 256 (4 colgroups x 64 edges)
    int* sRow = (int*)(sm + 27392);    // 64
    int* sCol = (int*)(sm + 27456);    // 64
    const float* hb = cur ? g_hB : g_hA;
    const int tid = threadIdx.x, tx = tid & 31, w = tid >> 5;
    const int E0 = ((w >> 2) << 5) + ((tx >> 3) << 3);
    const int C0 = ((w & 3) << 5) + ((tx & 7) << 2);
    const int jl = tx & 7;
    const int e0 = blockIdx.x * 64;

    if (tid < 128) { sAw[tid] = aw[tid]; sCw2[tid] = cw2[tid]; }
    if (tid < 64) {
        int e = e0 + tid;
        int r = edges[e], c = edges[NE + e];
        sRow[tid] = r; sCol[tid] = c;
        float dx = g_x[r * 3] - g_x[c * 3];
        float dy = g_x[r * 3 + 1] - g_x[c * 3 + 1];
        float dz = g_x[r * 3 + 2] - g_x[c * 3 + 2];
        sCD[tid * 3] = dx; sCD[tid * 3 + 1] = dy; sCD[tid * 3 + 2] = dz;
        sA[256 * 64 + tid] = dx * dx + dy * dy + dz * dz;  // xv=0 rows 256..258
        sA[257 * 64 + tid] = ea[e * 2];
        sA[258 * 64 + tid] = ea[e * 2 + 1];
    }
    for (int i = tid; i < 29 * 64; i += 256) sA[259 * 64 + i] = 0.f;
    __syncthreads();
    for (int it = tid; it < 2048; it += 256) {  // h[row] -> rows 0..127
        int e = it & 63, q = it >> 6;
        float4 v = *(const float4*)(hb + sRow[e] * HID + 4 * q);
        int p = e ^ ((q & 15) << 2);
        int kb = 4 * q * 64;
        sA[kb + p] = v.x; sA[kb + 64 + p] = v.y;
        sA[kb + 128 + p] = v.z; sA[kb + 192 + p] = v.w;
    }
    for (int it = tid; it < 2048; it += 256) {  // h[col] -> rows 128..255
        int e = it & 63, q = it >> 6;
        float4 v = *(const float4*)(hb + sCol[e] * HID + 4 * q);
        int p = e ^ ((q & 15) << 2);
        int kb = (128 + 4 * q) * 64;
        sA[kb + p] = v.x; sA[kb + 64 + p] = v.y;
        sA[kb + 128 + p] = v.z; sA[kb + 192 + p] = v.w;
    }

    float acc[8][4];
    // GEMM1: t1 = silu(e_in @ ew1 + eb1) -> rows 0..127
    gemm64(sA, sW, ew1, 259, 288, acc);
    store_out64(sA, 0, acc, eb1);
    // GEMM2: m = silu(t1 @ ew2 + eb2), attention gate (cross-warp dot)
    gemm64(sA, sW, ew2, 128, 128, acc);
    {
        float mv[8][4];
        float attp[8] = {0, 0, 0, 0, 0, 0, 0, 0};
#pragma unroll
        for (int j = 0; j < 4; j++) {
            int c = C0 + j;
            float b = eb2[c], wA = sAw[c];
#pragma unroll
            for (int e = 0; e < 8; e++) {
                mv[e][j] = siluf(acc[e][j] + b);
                attp[e] += mv[e][j] * wA;
            }
        }
#pragma unroll
        for (int e = 0; e < 8; e++) {
            float v = attp[e];
            v += __shfl_xor_sync(0xffffffffu, v, 1);
            v += __shfl_xor_sync(0xffffffffu, v, 2);
            v += __shfl_xor_sync(0xffffffffu, v, 4);
            attp[e] = v;
        }
        if (jl == 0) {
#pragma unroll
            for (int e = 0; e < 8; e++) sGp[(w & 3) * 64 + E0 + e] = attp[e];
        }
        __syncthreads();
        float abv = ab[0];
#pragma unroll
        for (int e = 0; e < 8; e++) {
            int E = E0 + e;
            float gate = sigf(sGp[E] + sGp[64 + E] + sGp[128 + E] + sGp[192 + E] + abv);
#pragma unroll
            for (int j = 0; j < 4; j++) mv[e][j] *= gate;
        }
#pragma unroll
        for (int j = 0; j < 4; j++) {  // gated m^T -> rows 128..255
            int c = C0 + j;
            int xvr = ((c >> 2) & 15) << 2;
            float* rp = sA + (128 + c) * 64;
            *(float4*)(rp + (E0 ^ xvr)) =
                make_float4(mv[0][j], mv[1][j], mv[2][j], mv[3][j]);
            *(float4*)(rp + ((E0 + 4) ^ xvr)) =
                make_float4(mv[4][j], mv[5][j], mv[6][j], mv[7][j]);
        }
        // agg_h: vectorized red straight from registers; drains under GEMM3
#pragma unroll
        for (int e = 0; e < 8; e++) {
            int ge = sRow[E0 + e];
            red4(&g_aggh[ge * HID + C0], mv[e][0], mv[e][1], mv[e][2], mv[e][3]);
        }
    }
    // GEMM3: t3 = silu(m @ cw1 + cb1); w = t3 @ cw2 (cross-warp dot)
    gemm64(sA + 128 * 64, sW, cw1, 128, 128, acc);
    {
        float wp[8] = {0, 0, 0, 0, 0, 0, 0, 0};
#pragma unroll
        for (int j = 0; j < 4; j++) {
            int c = C0 + j;
            float b = cb1[c], cw = sCw2[c];
#pragma unroll
            for (int e = 0; e < 8; e++) wp[e] += siluf(acc[e][j] + b) * cw;
        }
#pragma unroll
        for (int e = 0; e < 8; e++) {
            float v = wp[e];
            v += __shfl_xor_sync(0xffffffffu, v, 1);
            v += __shfl_xor_sync(0xffffffffu, v, 2);
            v += __shfl_xor_sync(0xffffffffu, v, 4);
            wp[e] = v;
        }
        if (jl == 0) {
#pragma unroll
            for (int e = 0; e < 8; e++) sGp[(w & 3) * 64 + E0 + e] = wp[e];
        }
    }
    __syncthreads();
    if (tid < 64) sWv[tid] = sGp[tid] + sGp[64 + tid] + sGp[128 + tid] + sGp[192 + tid];
    __syncthreads();
    if (tid < 192) {
        int e = tid / 3, d = tid - e * 3;
        atomicAdd(&g_aggx[sRow[e] * 3 + d], sCD[tid] * sWv[e]);
    }
}

__global__ void __launch_bounds__(256, 2) k_node(
    int cur, const float* __restrict__ nw1, const float* __restrict__ nb1,
    const float* __restrict__ nw2, const float* __restrict__ nb2,
    const float* __restrict__ vw1, const float* __restrict__ vb1,
    const float* __restrict__ vw2, const float* __restrict__ vb2) {
    extern __shared__ float sm[];
    float* sA = sm;               // 256 rows x 64
    float* sW = sm + 16384;       // 2 x 4096
    float* sS = sm + 24576;       // 64
    float* sVw2 = sm + 24640;     // 128
    float* sGp = sm + 24768;      // 256
    const float* hb = cur ? g_hB : g_hA;
    float* hn = cur ? g_hA : g_hB;
    const int tid = threadIdx.x, tx = tid & 31, w = tid >> 5;
    const int E0 = ((w >> 2) << 5) + ((tx >> 3) << 3);
    const int C0 = ((w & 3) << 5) + ((tx & 7) << 2);
    const int jl = tx & 7;
    const int n0 = blockIdx.x * 64;

    if (tid < 128) sVw2[tid] = vw2[tid];
    for (int it = tid; it < 2048; it += 256) {
        int e = it & 63, q = it >> 6;
        int n = n0 + e;
        float4 v = (n < NN) ? *(const float4*)(hb + n * HID + 4 * q)
                            : make_float4(0.f, 0.f, 0.f, 0.f);
        float4 a = (n < NN) ? *(const float4*)(g_aggh + n * HID + 4 * q)
                            : make_float4(0.f, 0.f, 0.f, 0.f);
        int p = e ^ ((q & 15) << 2);
        int kb = 4 * q * 64;
        sA[kb + p] = v.x; sA[kb + 64 + p] = v.y;
        sA[kb + 128 + p] = v.z; sA[kb + 192 + p] = v.w;
        int kb2 = (128 + 4 * q) * 64;
        sA[kb2 + p] = a.x; sA[kb2 + 64 + p] = a.y;
        sA[kb2 + 128 + p] = a.z; sA[kb2 + 192 + p] = a.w;
    }

    float acc[8][4];
    // velocity MLP: s = silu(h @ vw1 + vb1) @ vw2 + vb2 (cross-warp dot)
    gemm64(sA, sW, vw1, 128, 128, acc);
    {
        float sp[8] = {0, 0, 0, 0, 0, 0, 0, 0};
#pragma unroll
        for (int j = 0; j < 4; j++) {
            int c = C0 + j;
            float b = vb1[c], w2 = sVw2[c];
#pragma unroll
            for (int e = 0; e < 8; e++) sp[e] += siluf(acc[e][j] + b) * w2;
        }
#pragma unroll
        for (int e = 0; e < 8; e++) {
            float v = sp[e];
            v += __shfl_xor_sync(0xffffffffu, v, 1);
            v += __shfl_xor_sync(0xffffffffu, v, 2);
            v += __shfl_xor_sync(0xffffffffu, v, 4);
            sp[e] = v;
        }
        if (jl == 0) {
#pragma unroll
            for (int e = 0; e < 8; e++) sGp[(w & 3) * 64 + E0 + e] = sp[e];
        }
    }
    __syncthreads();
    if (tid < 64)
        sS[tid] = sGp[tid] + sGp[64 + tid] + sGp[128 + tid] + sGp[192 + tid] + vb2[0];
    __syncthreads();
    if (tid < 64) {
        int n = n0 + tid;
        if (n < NN) {
            float cnt = fmaxf(g_cnt[n], 1.f);
            float s = sS[tid];
#pragma unroll
            for (int d = 0; d < 3; d++) {
                float vn = s * g_vel[n * 3 + d];
                g_vel[n * 3 + d] = vn;
                g_x[n * 3 + d] += g_aggx[n * 3 + d] / cnt + vn;
            }
        }
    }
    // node MLP: h = silu([h, aggh] @ nw1 + nb1) @ nw2 + nb2
    gemm64(sA, sW, nw1, 256, 256, acc);
    store_out64(sA, 0, acc, nb1);
    gemm64(sA, sW, nw2, 128, 128, acc);
#pragma unroll
    for (int e = 0; e < 8; e++) {
        int n = n0 + E0 + e;
        if (n < NN) {
            float4 v;
            v.x = acc[e][0] + nb2[C0];
            v.y = acc[e][1] + nb2[C0 + 1];
            v.z = acc[e][2] + nb2[C0 + 2];
            v.w = acc[e][3] + nb2[C0 + 3];
            *(float4*)(hn + n * HID + C0) = v;
        }
    }
}

__global__ void k_proj(const float* __restrict__ pw, const float* __restrict__ pb,
                       float* __restrict__ out) {
    int i = blockIdx.x * blockDim.x + threadIdx.x;
    if (i < NN * 3) {
        int n = i / 3, p = i - n * 3;
        float s = pb[p];
        const float* hr = g_hA + n * HID;
#pragma unroll 16
        for (int k = 0; k < HID; k++) s += hr[k] * pw[k * 3 + p];
        out[i] = s;
    } else if (i < NN * 6) {
        out[i] = g_x[i - NN * 3];
    } else if (i < NN * 9) {
        out[i] = g_vel[i - NN * 6];
    }
}

extern "C" void kernel_launch(void* const* d_in, const int* in_sizes, int n_in,
                              void* d_out, int out_size) {
    const float* h_in = (const float*)d_in[0];
    const float* x_in = (const float*)d_in[1];
    const float* vel_in = (const float*)d_in[2];
    const float* ea = (const float*)d_in[3];
    const int* edges = (const int*)d_in[4];
    const float* emb_w = (const float*)d_in[5];
    const float* emb_b = (const float*)d_in[6];
    const float* ew1 = (const float*)d_in[7];
    const float* eb1 = (const float*)d_in[8];
    const float* ew2 = (const float*)d_in[9];
    const float* eb2 = (const float*)d_in[10];
    const float* aw = (const float*)d_in[11];
    const float* ab = (const float*)d_in[12];
    const float* nw1 = (const float*)d_in[13];
    const float* nb1 = (const float*)d_in[14];
    const float* nw2 = (const float*)d_in[15];
    const float* nb2 = (const float*)d_in[16];
    const float* cw1 = (const float*)d_in[17];
    const float* cb1 = (const float*)d_in[18];
    const float* cw2 = (const float*)d_in[19];
    const float* vw1 = (const float*)d_in[20];
    const float* vb1 = (const float*)d_in[21];
    const float* vw2 = (const float*)d_in[22];
    const float* vb2 = (const float*)d_in[23];
    const float* pw = (const float*)d_in[24];
    const float* pb = (const float*)d_in[25];

    const int SME = SME_FLOATS * 4;
    const int SMN = SMN_FLOATS * 4;
    cudaFuncSetAttribute(k_edge, cudaFuncAttributeMaxDynamicSharedMemorySize, SME);
    cudaFuncSetAttribute(k_node, cudaFuncAttributeMaxDynamicSharedMemorySize, SMN);

    k_setup<<<5000, 256>>>(h_in, x_in, vel_in, emb_w, emb_b);
    k_count<<<1250, 256>>>(edges);
    for (int i = 0; i < 4; i++) {
        k_zero<<<5000, 256>>>();
        k_edge<<<5000, 256, SME>>>(i & 1, ea, edges,
            ew1 + i * 259 * HID, eb1 + i * HID,
            ew2 + i * HID * HID, eb2 + i * HID,
            aw + i * HID, ab + i,
            cw1 + i * HID * HID, cb1 + i * HID, cw2 + i * HID);
        k_node<<<157, 256, SMN>>>(i & 1,
            nw1 + i * 256 * HID, nb1 + i * HID,
            nw2 + i * HID * HID, nb2 + i * HID,
            vw1 + i * HID * HID, vb1 + i * HID,
            vw2 + i * HID, vb2 + i);
    }
    k_proj<<<(NN * 9 + 255) / 256, 256>>>(pw, pb, (float*)d_out);
}

// round 15
// speedup vs baseline: 1.1417x; 1.1417x over previous
#include <cuda_runtime.h>

#define NN 10000
#define NE 320000
#define HID 128
#define SME_BYTES 103936
#define SMN_FLOATS 24768
// per-layer perm block (hi+lo per chunk, 8192 floats/chunk):
// ew1 9 chunks = 73728, ew2 4 = 32768, cw1 4 = 32768 ; total 139264
#define WP_L 139264
#define WP_EW2 73728
#define WP_CW1 106496

__device__ float g_hA[NN * HID];
__device__ float g_hB[NN * HID];
__device__ float g_x[NN * 3];
__device__ float g_vel[NN * 3];
__device__ float g_aggx[NN * 3];
__device__ float g_aggh[NN * HID];
__device__ float g_cnt[NN];
__device__ float g_wp[4 * WP_L];

__device__ __forceinline__ float siluf(float v) {
    return v * __fdividef(1.f, 1.f + __expf(-v));
}
__device__ __forceinline__ float sigf(float v) {
    return __fdividef(1.f, 1.f + __expf(-v));
}
__device__ __forceinline__ unsigned long long pack2(float v) {
    unsigned long long r;
    asm("mov.b64 %0, {%1, %1};" : "=l"(r) : "f"(v));
    return r;
}
__device__ __forceinline__ void unpack2(unsigned long long p, float& a, float& b) {
    asm("mov.b64 {%0, %1}, %2;" : "=f"(a), "=f"(b) : "l"(p));
}
__device__ __forceinline__ void ffma2(unsigned long long& d, unsigned long long a,
                                      unsigned long long b) {
    asm("fma.rn.f32x2 %0, %1, %2, %0;" : "+l"(d) : "l"(a), "l"(b));
}
__device__ __forceinline__ void red2(float* p, float a, float b) {
    asm volatile("red.global.add.v2.f32 [%0], {%1, %2};"
                 :: "l"(p), "f"(a), "f"(b) : "memory");
}
__device__ __forceinline__ unsigned tf32r(float f) {
    unsigned t;
    asm("cvt.rna.tf32.f32 %0, %1;" : "=r"(t) : "f"(f));
    return t;
}
__device__ __forceinline__ unsigned tf32lo(float v, unsigned hi) {
    return tf32r(v - __uint_as_float(hi));
}
// m16n8k8 tf32 HMMA, D += A*B (fp32 accum)
__device__ __forceinline__ void mma8(float* d, uint4 a, uint2 b) {
    asm volatile(
        "mma.sync.aligned.m16n8k8.row.col.f32.tf32.tf32.f32 "
        "{%0,%1,%2,%3}, {%4,%5,%6,%7}, {%8,%9}, {%0,%1,%2,%3};"
        : "+f"(d[0]), "+f"(d[1]), "+f"(d[2]), "+f"(d[3])
        : "r"(a.x), "r"(a.y), "r"(a.z), "r"(a.w), "r"(b.x), "r"(b.y));
}

// Permuted hi/lo tf32 weights. Per chunk 8192 floats: hi[4096] then lo[4096].
// Within a half: float index ((c*16+t)*32+l)*2+j <-> B[k][n],
// k = 32ci+8c+(l&3)+4j, n = 8t+(l>>2). Zero past K.
__global__ void k_permw(const float* __restrict__ ew1, const float* __restrict__ ew2,
                        const float* __restrict__ cw1) {
    int idx = blockIdx.x * 256 + threadIdx.x;
    if (idx >= 4 * WP_L) return;
    int layer = idx / WP_L, rem = idx % WP_L;
    const float* src; int K, local;
    if (rem < WP_EW2) { src = ew1 + layer * 259 * HID; K = 259; local = rem; }
    else if (rem < WP_CW1) { src = ew2 + layer * HID * HID; K = 128; local = rem - WP_EW2; }
    else { src = cw1 + layer * HID * HID; K = 128; local = rem - WP_CW1; }
    int ci = local >> 13, r13 = local & 8191;
    int half = r13 >> 12, r12 = r13 & 4095;
    int c = r12 >> 10, t = (r12 >> 6) & 15, l = (r12 >> 1) & 31, j = r12 & 1;
    int k = 32 * ci + 8 * c + (l & 3) + 4 * j;
    int n = 8 * t + (l >> 2);
    float v = (k < K) ? src[k * HID + n] : 0.f;
    unsigned hi = tf32r(v);
    g_wp[idx] = __uint_as_float(half ? tf32lo(v, hi) : hi);
}

__global__ void k_setup(const float* __restrict__ h_in, const float* __restrict__ x_in,
                        const float* __restrict__ vel_in, const float* __restrict__ emb_w,
                        const float* __restrict__ emb_b) {
    int i = blockIdx.x * blockDim.x + threadIdx.x;
    if (i < NN * 3) { g_x[i] = x_in[i]; g_vel[i] = vel_in[i]; }
    if (i < NN) g_cnt[i] = 0.f;
    if (i < NN * HID) {
        int n = i >> 7, c = i & 127;
        float s = emb_b[c];
#pragma unroll
        for (int k = 0; k < 6; k++) s += h_in[n * 6 + k] * emb_w[k * HID + c];
        g_hA[i] = s;
    }
}

__global__ void k_count(const int* __restrict__ edges) {
    int e = blockIdx.x * blockDim.x + threadIdx.x;
    if (e < NE) atomicAdd(&g_cnt[edges[e]], 1.f);
}

__global__ void k_zero() {
    int i = blockIdx.x * blockDim.x + threadIdx.x;
    if (i < NN * 3) g_aggx[i] = 0.f;
    if (i < NN * HID) g_aggh[i] = 0.f;
}

// Quad-shuffle transpose of D-fragments into hi/lo A-fragments -> sAfull.
__device__ __forceinline__ void transpose_store(float* sAfull, float acc[8][4],
                                                int eg, int cg, int lane) {
    int m = lane & 3;
    int s0 = (lane & ~3) | (m >> 1), s1 = s0 + 2;
    bool odd = m & 1;
#pragma unroll
    for (int t = 0; t < 8; t++) {
        float u0 = __shfl_sync(0xffffffffu, acc[t][0], s0);
        float u1 = __shfl_sync(0xffffffffu, acc[t][1], s0);
        float u2 = __shfl_sync(0xffffffffu, acc[t][2], s0);
        float u3 = __shfl_sync(0xffffffffu, acc[t][3], s0);
        float w0 = __shfl_sync(0xffffffffu, acc[t][0], s1);
        float w1 = __shfl_sync(0xffffffffu, acc[t][1], s1);
        float w2 = __shfl_sync(0xffffffffu, acc[t][2], s1);
        float w3 = __shfl_sync(0xffffffffu, acc[t][3], s1);
        float v0 = odd ? u1 : u0, v1 = odd ? u3 : u2;
        float v2 = odd ? w1 : w0, v3 = odd ? w3 : w2;
        uint4 hi = make_uint4(tf32r(v0), tf32r(v1), tf32r(v2), tf32r(v3));
        uint4 lo = make_uint4(tf32lo(v0, hi.x), tf32lo(v1, hi.y),
                              tf32lo(v2, hi.z), tf32lo(v3, hi.w));
        int ci2 = 2 * cg + (t >> 2), c = t & 3;
        int ofs = (((ci2 * 4 + c) * 4 + eg) * 32 + lane) * 4;
        *(uint4*)(sAfull + ofs) = hi;
        *(uint4*)(sAfull + 8192 + ofs) = lo;
    }
}

// Fused edge kernel, 3xTF32 mma.sync. 64 edges/CTA, grid 5000, 256 threads.
__global__ void __launch_bounds__(256, 2) k_edge_mma(
    int cur, int layer, const float* __restrict__ ea, const int* __restrict__ edges,
    const float* __restrict__ eb1, const float* __restrict__ eb2,
    const float* __restrict__ aw, const float* __restrict__ ab,
    const float* __restrict__ cb1, const float* __restrict__ cw2) {
    extern __shared__ float sm[];
    float* sAfull = sm;           // 16384 (hi 8192, lo 8192); GEMM1 A-chunk aliased at sm
    float* sAc = sm;              // GEMM1 chunk: hi 2048, lo 2048
    float* sBc = sm + 16384;      // 8192 (hi 4096, lo 4096)
    float* sEb1 = sm + 24576;
    float* sEb2 = sm + 24704;
    float* sAw = sm + 24832;
    float* sCb1 = sm + 24960;
    float* sCw2 = sm + 25088;
    float* sEa = sm + 25216;      // 128
    int* sRow = (int*)(sm + 25344);
    int* sCol = (int*)(sm + 25408);
    float* sCD = sm + 25472;      // 192
    float* sRad = sm + 25664;     // 64
    float* sGp = sm + 25728;      // 128
    float* sWv = sm + 25856;      // 64
    const float* hb = cur ? g_hB : g_hA;
    const float* wp1 = g_wp + layer * WP_L;
    const float* wp2 = wp1 + WP_EW2;
    const float* wp3 = wp1 + WP_CW1;
    const int tid = threadIdx.x, lane = tid & 31, wid = tid >> 5;
    const int eg = wid >> 1, cg = wid & 1;
    const int e0 = blockIdx.x * 64;

    if (tid < 128) {
        sEb1[tid] = eb1[tid]; sEb2[tid] = eb2[tid]; sAw[tid] = aw[tid];
        sCb1[tid] = cb1[tid]; sCw2[tid] = cw2[tid];
        sEa[tid] = ea[e0 * 2 + tid];
    }
    if (tid < 64) {
        int e = e0 + tid;
        int r = edges[e], c = edges[NE + e];
        sRow[tid] = r; sCol[tid] = c;
        float dx = g_x[r * 3] - g_x[c * 3];
        float dy = g_x[r * 3 + 1] - g_x[c * 3 + 1];
        float dz = g_x[r * 3 + 2] - g_x[c * 3 + 2];
        sCD[tid * 3] = dx; sCD[tid * 3 + 1] = dy; sCD[tid * 3 + 2] = dz;
        sRad[tid] = dx * dx + dy * dy + dz * dz;
    }
    float abv = ab[0];
    __syncthreads();

    float acc[8][4];
#pragma unroll
    for (int t = 0; t < 8; t++)
#pragma unroll
        for (int i = 0; i < 4; i++) acc[t][i] = 0.f;

    uint4 ra[4];   // hi[2], lo[2]
    float4 rb[8];  // hi[4], lo[4]
#define LDA1(ci)                                                              \
    {                                                                         \
        _Pragma("unroll") for (int s2 = 0; s2 < 2; s2++) {                    \
            int s = tid + 256 * s2;                                           \
            int c = s >> 7, g = (s >> 5) & 3, l = s & 31;                     \
            int e1 = 16 * g + (l >> 2);                                       \
            float a0, a1, a2, a3;                                             \
            if ((ci) < 8) {                                                   \
                const int* sI = ((ci) < 4) ? sRow : sCol;                     \
                int n1 = sI[e1] * HID, n2 = sI[e1 + 8] * HID;                 \
                int kb = 32 * ((ci) & 3) + 8 * c + (l & 3);                   \
                a0 = hb[n1 + kb]; a1 = hb[n2 + kb];                           \
                a2 = hb[n1 + kb + 4]; a3 = hb[n2 + kb + 4];                   \
            } else {                                                          \
                a0 = a1 = a2 = a3 = 0.f;                                      \
                int kin = l & 3;                                              \
                if (c == 0 && kin < 3) {                                      \
                    a0 = (kin == 0) ? sRad[e1] : sEa[e1 * 2 + kin - 1];       \
                    a1 = (kin == 0) ? sRad[e1 + 8] : sEa[(e1 + 8) * 2 + kin - 1]; \
                }                                                             \
            }                                                                 \
            uint4 h4 = make_uint4(tf32r(a0), tf32r(a1), tf32r(a2), tf32r(a3)); \
            ra[s2] = h4;                                                      \
            ra[2 + s2] = make_uint4(tf32lo(a0, h4.x), tf32lo(a1, h4.y),       \
                                    tf32lo(a2, h4.z), tf32lo(a3, h4.w));      \
        }                                                                     \
    }
#define LDB(wp, ci)                                                           \
    {                                                                         \
        const float4* src = (const float4*)((wp) + (ci) * 8192);              \
        _Pragma("unroll") for (int i = 0; i < 8; i++) rb[i] = src[tid + 256 * i]; \
    }
#define STA()                                                                 \
    {                                                                         \
        uint4* da = (uint4*)sAc;                                              \
        da[tid] = ra[0]; da[tid + 256] = ra[1];                               \
        da[tid + 512] = ra[2]; da[tid + 768] = ra[3];                         \
    }
#define STB()                                                                 \
    {                                                                         \
        float4* db = (float4*)sBc;                                            \
        _Pragma("unroll") for (int i = 0; i < 8; i++) db[tid + 256 * i] = rb[i]; \
    }
#define MMA_TILE(sa, aofs, loofs)                                             \
    _Pragma("unroll") for (int c = 0; c < 4; c++) {                           \
        uint4 ahi = *(const uint4*)((sa) + (aofs));                           \
        uint4 alo = *(const uint4*)((sa) + (aofs) + (loofs));                 \
        _Pragma("unroll") for (int t = 0; t < 8; t++) {                       \
            int bofs = ((c * 16 + 8 * cg + t) * 32 + lane) * 2;               \
            uint2 bhi = *(const uint2*)(sBc + bofs);                          \
            uint2 blo = *(const uint2*)(sBc + 4096 + bofs);                   \
            mma8(acc[t], ahi, bhi);                                           \
            mma8(acc[t], alo, bhi);                                           \
            mma8(acc[t], ahi, blo);                                           \
        }                                                                     \
    }

    // ---- GEMM1: t1 = e_in @ ew1 (K=259, 9 chunks) ----
    LDA1(0); LDB(wp1, 0);
    STA(); STB();
    for (int ci = 0; ci < 9; ci++) {
        __syncthreads();
        bool more = ci < 8;
        if (more) { LDA1(ci + 1); LDB(wp1, ci + 1); }
        MMA_TILE(sAc, ((c * 4 + eg) * 32 + lane) * 4, 2048);
        __syncthreads();
        if (more) { STA(); STB(); }
    }
    // epilogue1: silu(+eb1) -> hi/lo fragments in sAfull
#pragma unroll
    for (int t = 0; t < 8; t++) {
        int c0 = 64 * cg + 8 * t + 2 * (lane & 3);
        float b0 = sEb1[c0], b1 = sEb1[c0 + 1];
        acc[t][0] = siluf(acc[t][0] + b0); acc[t][1] = siluf(acc[t][1] + b1);
        acc[t][2] = siluf(acc[t][2] + b0); acc[t][3] = siluf(acc[t][3] + b1);
    }
    transpose_store(sAfull, acc, eg, cg, lane);
#pragma unroll
    for (int t = 0; t < 8; t++)
#pragma unroll
        for (int i = 0; i < 4; i++) acc[t][i] = 0.f;

    // ---- GEMM2: m_raw = t1 @ ew2 (4 chunks) ----
    LDB(wp2, 0); STB();
    for (int ci = 0; ci < 4; ci++) {
        __syncthreads();
        if (ci < 3) LDB(wp2, ci + 1);
        MMA_TILE(sAfull, (((ci * 4 + c) * 4 + eg) * 32 + lane) * 4, 8192);
        __syncthreads();
        if (ci < 3) STB();
    }
    // epilogue2: m = silu(+eb2); gate; scale; agg_h red2; -> sAfull
    {
        float p0 = 0.f, p1 = 0.f;
#pragma unroll
        for (int t = 0; t < 8; t++) {
            int c0 = 64 * cg + 8 * t + 2 * (lane & 3);
            float b0 = sEb2[c0], b1 = sEb2[c0 + 1];
            float w0 = sAw[c0], w1 = sAw[c0 + 1];
            acc[t][0] = siluf(acc[t][0] + b0); acc[t][1] = siluf(acc[t][1] + b1);
            acc[t][2] = siluf(acc[t][2] + b0); acc[t][3] = siluf(acc[t][3] + b1);
            p0 += acc[t][0] * w0 + acc[t][1] * w1;
            p1 += acc[t][2] * w0 + acc[t][3] * w1;
        }
        p0 += __shfl_xor_sync(0xffffffffu, p0, 1);
        p0 += __shfl_xor_sync(0xffffffffu, p0, 2);
        p1 += __shfl_xor_sync(0xffffffffu, p1, 1);
        p1 += __shfl_xor_sync(0xffffffffu, p1, 2);
        int E = 16 * eg + (lane >> 2);
        if ((lane & 3) == 0) {
            sGp[cg * 64 + E] = p0;
            sGp[cg * 64 + E + 8] = p1;
        }
        __syncthreads();
        float g0 = sigf(sGp[E] + sGp[64 + E] + abv);
        float g1 = sigf(sGp[E + 8] + sGp[64 + E + 8] + abv);
        int ge1 = sRow[E] * HID, ge2 = sRow[E + 8] * HID;
#pragma unroll
        for (int t = 0; t < 8; t++) {
            int c0 = 64 * cg + 8 * t + 2 * (lane & 3);
            acc[t][0] *= g0; acc[t][1] *= g0;
            acc[t][2] *= g1; acc[t][3] *= g1;
            red2(&g_aggh[ge1 + c0], acc[t][0], acc[t][1]);
            red2(&g_aggh[ge2 + c0], acc[t][2], acc[t][3]);
        }
        transpose_store(sAfull, acc, eg, cg, lane);
#pragma unroll
        for (int t = 0; t < 8; t++)
#pragma unroll
            for (int i = 0; i < 4; i++) acc[t][i] = 0.f;
    }

    // ---- GEMM3: t3_raw = m @ cw1 (4 chunks) ----
    LDB(wp3, 0); STB();
    for (int ci = 0; ci < 4; ci++) {
        __syncthreads();
        if (ci < 3) LDB(wp3, ci + 1);
        MMA_TILE(sAfull, (((ci * 4 + c) * 4 + eg) * 32 + lane) * 4, 8192);
        __syncthreads();
        if (ci < 3) STB();
    }
    // epilogue3: w = silu(+cb1) . cw2 ; agg_x
    {
        float p0 = 0.f, p1 = 0.f;
#pragma unroll
        for (int t = 0; t < 8; t++) {
            int c0 = 64 * cg + 8 * t + 2 * (lane & 3);
            p0 += siluf(acc[t][0] + sCb1[c0]) * sCw2[c0]
                + siluf(acc[t][1] + sCb1[c0 + 1]) * sCw2[c0 + 1];
            p1 += siluf(acc[t][2] + sCb1[c0]) * sCw2[c0]
                + siluf(acc[t][3] + sCb1[c0 + 1]) * sCw2[c0 + 1];
        }
        p0 += __shfl_xor_sync(0xffffffffu, p0, 1);
        p0 += __shfl_xor_sync(0xffffffffu, p0, 2);
        p1 += __shfl_xor_sync(0xffffffffu, p1, 1);
        p1 += __shfl_xor_sync(0xffffffffu, p1, 2);
        int E = 16 * eg + (lane >> 2);
        if ((lane & 3) == 0) {
            sGp[cg * 64 + E] = p0;
            sGp[cg * 64 + E + 8] = p1;
        }
    }
    __syncthreads();
    if (tid < 64) sWv[tid] = sGp[tid] + sGp[64 + tid];
    __syncthreads();
    if (tid < 192) {
        int e = tid / 3, d = tid - e * 3;
        atomicAdd(&g_aggx[sRow[e] * 3 + d], sCD[tid] * sWv[e]);
    }
#undef LDA1
#undef LDB
#undef STA
#undef STB
#undef MMA_TILE
}

// ---------------- scalar node kernel (proven R9 path) ----------------
__device__ __forceinline__ void gemm64(const float* sA, float* sW,
                                       const float* __restrict__ gW,
                                       int K, int Kpad, float acc[8][4]) {
    const int tid = threadIdx.x, tx = tid & 31, ty = tid >> 5;
    unsigned long long a2[4][4];
#pragma unroll
    for (int p = 0; p < 4; p++)
#pragma unroll
        for (int j = 0; j < 4; j++) a2[p][j] = 0ULL;
    const float4* __restrict__ gW4 = (const float4*)gW;
    const int nch = Kpad >> 5;
    float4 r[4];
#pragma unroll
    for (int i = 0; i < 4; i++) {
        int f = tid + i * 256;
        int rr = f >> 5;
        r[i] = (rr < K) ? gW4[rr * 32 + (f & 31)] : make_float4(0.f, 0.f, 0.f, 0.f);
    }
#pragma unroll
    for (int i = 0; i < 4; i++) ((float4*)sW)[tid + i * 256] = r[i];
    for (int ci = 0; ci < nch; ci++) {
        __syncthreads();
        const int kb = ci << 5;
        const float* buf = sW + ((ci & 1) << 12);
        const bool more = (ci + 1 < nch);
        if (more) {
#pragma unroll
            for (int i = 0; i < 4; i++) {
                int f = tid + i * 256;
                int rr = kb + 32 + (f >> 5);
                r[i] = (rr < K) ? gW4[rr * 32 + (f & 31)]
                                : make_float4(0.f, 0.f, 0.f, 0.f);
            }
        }
#pragma unroll 8
        for (int kk = 0; kk < 32; kk++) {
            int k = kb + kk;
            int rot = ((k >> 2) & 15) << 2;
            const float* ar = sA + k * 64;
            ulonglong2 a0 = *(const ulonglong2*)(ar + ((8 * ty + rot) & 63));
            ulonglong2 a1 = *(const ulonglong2*)(ar + ((8 * ty + 4 + rot) & 63));
            float4 w = *(const float4*)(buf + kk * 128 + 4 * tx);
            unsigned long long w0 = pack2(w.x), w1 = pack2(w.y);
            unsigned long long w2 = pack2(w.z), w3 = pack2(w.w);
            ffma2(a2[0][0], a0.x, w0); ffma2(a2[0][1], a0.x, w1);
            ffma2(a2[0][2], a0.x, w2); ffma2(a2[0][3], a0.x, w3);
            ffma2(a2[1][0], a0.y, w0); ffma2(a2[1][1], a0.y, w1);
            ffma2(a2[1][2], a0.y, w2); ffma2(a2[1][3], a0.y, w3);
            ffma2(a2[2][0], a1.x, w0); ffma2(a2[2][1], a1.x, w1);
            ffma2(a2[2][2], a1.x, w2); ffma2(a2[2][3], a1.x, w3);
            ffma2(a2[3][0], a1.y, w0); ffma2(a2[3][1], a1.y, w1);
            ffma2(a2[3][2], a1.y, w2); ffma2(a2[3][3], a1.y, w3);
        }
        if (more) {
            float* nb = sW + (((ci + 1) & 1) << 12);
#pragma unroll
            for (int i = 0; i < 4; i++) ((float4*)nb)[tid + i * 256] = r[i];
        }
    }
#pragma unroll
    for (int p = 0; p < 4; p++)
#pragma unroll
        for (int j = 0; j < 4; j++) unpack2(a2[p][j], acc[2 * p][j], acc[2 * p + 1][j]);
    __syncthreads();
}

__device__ __forceinline__ void store_out64(float* sA, int baseRow, float acc[8][4],
                                            const float* __restrict__ bias) {
    const int tid = threadIdx.x, tx = tid & 31, ty = tid >> 5;
#pragma unroll
    for (int j = 0; j < 4; j++) {
        int c = 4 * tx + j;
        float b = bias[c];
        int rot = ((c >> 2) & 15) << 2;
        float* rp = sA + (baseRow + c) * 64;
        float4 v0, v1;
        v0.x = siluf(acc[0][j] + b); v0.y = siluf(acc[1][j] + b);
        v0.z = siluf(acc[2][j] + b); v0.w = siluf(acc[3][j] + b);
        v1.x = siluf(acc[4][j] + b); v1.y = siluf(acc[5][j] + b);
        v1.z = siluf(acc[6][j] + b); v1.w = siluf(acc[7][j] + b);
        *(float4*)(rp + ((8 * ty + rot) & 63)) = v0;
        *(float4*)(rp + ((8 * ty + 4 + rot) & 63)) = v1;
    }
}

__global__ void __launch_bounds__(256, 2) k_node(
    int cur, const float* __restrict__ nw1, const float* __restrict__ nb1,
    const float* __restrict__ nw2, const float* __restrict__ nb2,
    const float* __restrict__ vw1, const float* __restrict__ vb1,
    const float* __restrict__ vw2, const float* __restrict__ vb2) {
    extern __shared__ float sm[];
    float* sA = sm;
    float* sW = sm + 16384;
    float* sS = sm + 24576;
    float* sVw2 = sm + 24640;
    const float* hb = cur ? g_hB : g_hA;
    float* hn = cur ? g_hA : g_hB;
    const int tid = threadIdx.x, tx = tid & 31, ty = tid >> 5;
    const int n0 = blockIdx.x * 64;

    if (tid < 128) sVw2[tid] = vw2[tid];
    for (int it = tid; it < 2048; it += 256) {
        int e = it & 63, q = it >> 6;
        int n = n0 + e;
        float4 v = (n < NN) ? *(const float4*)(hb + n * HID + 4 * q)
                            : make_float4(0.f, 0.f, 0.f, 0.f);
        float4 a = (n < NN) ? *(const float4*)(g_aggh + n * HID + 4 * q)
                            : make_float4(0.f, 0.f, 0.f, 0.f);
        int p = (e + ((q & 15) << 2)) & 63;
        int kb = 4 * q * 64;
        sA[kb + p] = v.x; sA[kb + 64 + p] = v.y;
        sA[kb + 128 + p] = v.z; sA[kb + 192 + p] = v.w;
        int kb2 = (128 + 4 * q) * 64;
        sA[kb2 + p] = a.x; sA[kb2 + 64 + p] = a.y;
        sA[kb2 + 128 + p] = a.z; sA[kb2 + 192 + p] = a.w;
    }

    float acc[8][4];
    gemm64(sA, sW, vw1, 128, 128, acc);
    {
        float sp[8] = {0, 0, 0, 0, 0, 0, 0, 0};
#pragma unroll
        for (int j = 0; j < 4; j++) {
            int c = 4 * tx + j;
            float b = vb1[c], w2 = sVw2[c];
#pragma unroll
            for (int e = 0; e < 8; e++) sp[e] += siluf(acc[e][j] + b) * w2;
        }
        float vb2s = vb2[0];
#pragma unroll
        for (int e = 0; e < 8; e++) {
            float v = sp[e];
            v += __shfl_xor_sync(0xffffffffu, v, 16);
            v += __shfl_xor_sync(0xffffffffu, v, 8);
            v += __shfl_xor_sync(0xffffffffu, v, 4);
            v += __shfl_xor_sync(0xffffffffu, v, 2);
            v += __shfl_xor_sync(0xffffffffu, v, 1);
            if (tx == 0) sS[8 * ty + e] = v + vb2s;
        }
    }
    __syncthreads();
    if (tid < 64) {
        int n = n0 + tid;
        if (n < NN) {
            float cnt = fmaxf(g_cnt[n], 1.f);
            float s = sS[tid];
#pragma unroll
            for (int d = 0; d < 3; d++) {
                float vn = s * g_vel[n * 3 + d];
                g_vel[n * 3 + d] = vn;
                g_x[n * 3 + d] += g_aggx[n * 3 + d] / cnt + vn;
            }
        }
    }
    gemm64(sA, sW, nw1, 256, 256, acc);
    store_out64(sA, 0, acc, nb1);
    gemm64(sA, sW, nw2, 128, 128, acc);
#pragma unroll
    for (int e = 0; e < 8; e++) {
        int n = n0 + 8 * ty + e;
        if (n < NN) {
            float4 v;
            v.x = acc[e][0] + nb2[4 * tx];
            v.y = acc[e][1] + nb2[4 * tx + 1];
            v.z = acc[e][2] + nb2[4 * tx + 2];
            v.w = acc[e][3] + nb2[4 * tx + 3];
            *(float4*)(hn + n * HID + 4 * tx) = v;
        }
    }
}

__global__ void k_proj(const float* __restrict__ pw, const float* __restrict__ pb,
                       float* __restrict__ out) {
    int i = blockIdx.x * blockDim.x + threadIdx.x;
    if (i < NN * 3) {
        int n = i / 3, p = i - n * 3;
        float s = pb[p];
        const float* hr = g_hA + n * HID;
#pragma unroll 16
        for (int k = 0; k < HID; k++) s += hr[k] * pw[k * 3 + p];
        out[i] = s;
    } else if (i < NN * 6) {
        out[i] = g_x[i - NN * 3];
    } else if (i < NN * 9) {
        out[i] = g_vel[i - NN * 6];
    }
}

extern "C" void kernel_launch(void* const* d_in, const int* in_sizes, int n_in,
                              void* d_out, int out_size) {
    const float* h_in = (const float*)d_in[0];
    const float* x_in = (const float*)d_in[1];
    const float* vel_in = (const float*)d_in[2];
    const float* ea = (const float*)d_in[3];
    const int* edges = (const int*)d_in[4];
    const float* emb_w = (const float*)d_in[5];
    const float* emb_b = (const float*)d_in[6];
    const float* ew1 = (const float*)d_in[7];
    const float* eb1 = (const float*)d_in[8];
    const float* ew2 = (const float*)d_in[9];
    const float* eb2 = (const float*)d_in[10];
    const float* aw = (const float*)d_in[11];
    const float* ab = (const float*)d_in[12];
    const float* nw1 = (const float*)d_in[13];
    const float* nb1 = (const float*)d_in[14];
    const float* nw2 = (const float*)d_in[15];
    const float* nb2 = (const float*)d_in[16];
    const float* cw1 = (const float*)d_in[17];
    const float* cb1 = (const float*)d_in[18];
    const float* cw2 = (const float*)d_in[19];
    const float* vw1 = (const float*)d_in[20];
    const float* vb1 = (const float*)d_in[21];
    const float* vw2 = (const float*)d_in[22];
    const float* vb2 = (const float*)d_in[23];
    const float* pw = (const float*)d_in[24];
    const float* pb = (const float*)d_in[25];

    const int SMN = SMN_FLOATS * 4;
    cudaFuncSetAttribute(k_edge_mma, cudaFuncAttributeMaxDynamicSharedMemorySize, SME_BYTES);
    cudaFuncSetAttribute(k_node, cudaFuncAttributeMaxDynamicSharedMemorySize, SMN);

    k_setup<<<5000, 256>>>(h_in, x_in, vel_in, emb_w, emb_b);
    k_count<<<1250, 256>>>(edges);
    k_permw<<<2176, 256>>>(ew1, ew2, cw1);
    for (int i = 0; i < 4; i++) {
        k_zero<<<5000, 256>>>();
        k_edge_mma<<<5000, 256, SME_BYTES>>>(i & 1, i, ea, edges,
            eb1 + i * HID, eb2 + i * HID, aw + i * HID, ab + i,
            cb1 + i * HID, cw2 + i * HID);
        k_node<<<157, 256, SMN>>>(i & 1,
            nw1 + i * 256 * HID, nb1 + i * HID,
            nw2 + i * HID * HID, nb2 + i * HID,
            vw1 + i * HID * HID, vb1 + i * HID,
            vw2 + i * HID, vb2 + i);
    }
    k_proj<<<(NN * 9 + 255) / 256, 256>>>(pw, pb, (float*)d_out);
}

// round 17
// speedup vs baseline: 2.1451x; 1.8789x over previous
#include <cuda_runtime.h>
#include <cuda_bf16.h>

#define NN 10000
#define NE 320000
#define HID 128
#define SME_BYTES 90112
#define SMN_FLOATS 24768
// per-layer perm block (packed bf16x2 hi+mid, 4096 floats/chunk):
// ew1 9 chunks = 36864, ew2 4 = 16384, cw1 4 = 16384 ; total 69632
#define WP_L 69632
#define WP_EW2 36864
#define WP_CW1 53248

__device__ float g_hA[NN * HID];
__device__ float g_hB[NN * HID];
__device__ float g_x[NN * 3];
__device__ float g_vel[NN * 3];
__device__ float g_aggx[NN * 3];
__device__ float g_aggh[NN * HID];
__device__ float g_cnt[NN];
__device__ float g_wp[4 * WP_L];

__device__ __forceinline__ float siluf(float v) {
    return v * __fdividef(1.f, 1.f + __expf(-v));
}
__device__ __forceinline__ float sigf(float v) {
    return __fdividef(1.f, 1.f + __expf(-v));
}
__device__ __forceinline__ unsigned long long pack2(float v) {
    unsigned long long r;
    asm("mov.b64 %0, {%1, %1};" : "=l"(r) : "f"(v));
    return r;
}
__device__ __forceinline__ void unpack2(unsigned long long p, float& a, float& b) {
    asm("mov.b64 {%0, %1}, %2;" : "=f"(a), "=f"(b) : "l"(p));
}
__device__ __forceinline__ void ffma2(unsigned long long& d, unsigned long long a,
                                      unsigned long long b) {
    asm("fma.rn.f32x2 %0, %1, %2, %0;" : "+l"(d) : "l"(a), "l"(b));
}
__device__ __forceinline__ void red2(float* p, float a, float b) {
    asm volatile("red.global.add.v2.f32 [%0], {%1, %2};"
                 :: "l"(p), "f"(a), "f"(b) : "memory");
}
__device__ __forceinline__ float bfh(float v) {
    return __bfloat162float(__float2bfloat16(v));
}
// pack two bf16: lo -> bits[15:0], hi -> bits[31:16]
__device__ __forceinline__ unsigned packbf(float lo, float hi) {
    unsigned r;
    asm("cvt.rn.bf16x2.f32 %0, %1, %2;" : "=r"(r) : "f"(hi), "f"(lo));
    return r;
}
// m16n8k16 bf16 HMMA, D += A*B (fp32 accum)
__device__ __forceinline__ void mma16(float* d, uint4 a, uint2 b) {
    asm volatile(
        "mma.sync.aligned.m16n8k16.row.col.f32.bf16.bf16.f32 "
        "{%0,%1,%2,%3}, {%4,%5,%6,%7}, {%8,%9}, {%0,%1,%2,%3};"
        : "+f"(d[0]), "+f"(d[1]), "+f"(d[2]), "+f"(d[3])
        : "r"(a.x), "r"(a.y), "r"(a.z), "r"(a.w), "r"(b.x), "r"(b.y));
}

// Permuted bf16x2 B-fragments, hi half then mid half per 32-k chunk.
// chunk float u: half=u>>11; u2=u&2047: breg=u2&1, l=(u2>>1)&31,
// t=(u2>>6)&15, ks=u2>>10. k0 = 32ci+16ks+8breg+2(l&3); n = 8t+(l>>2).
// value = pack(elem k0, elem k0+1).
__global__ void k_permw(const float* __restrict__ ew1, const float* __restrict__ ew2,
                        const float* __restrict__ cw1) {
    int idx = blockIdx.x * 256 + threadIdx.x;
    if (idx >= 4 * WP_L) return;
    int layer = idx / WP_L, rem = idx % WP_L;
    const float* src; int K, local;
    if (rem < WP_EW2) { src = ew1 + layer * 259 * HID; K = 259; local = rem; }
    else if (rem < WP_CW1) { src = ew2 + layer * HID * HID; K = 128; local = rem - WP_EW2; }
    else { src = cw1 + layer * HID * HID; K = 128; local = rem - WP_CW1; }
    int ci = local >> 12, r12 = local & 4095;
    int half = r12 >> 11, u2 = r12 & 2047;
    int breg = u2 & 1, l = (u2 >> 1) & 31, t = (u2 >> 6) & 15, ks = u2 >> 10;
    int k0 = 32 * ci + 16 * ks + 8 * breg + 2 * (l & 3);
    int n = 8 * t + (l >> 2);
    float v0 = (k0 < K) ? src[k0 * HID + n] : 0.f;
    float v1 = (k0 + 1 < K) ? src[(k0 + 1) * HID + n] : 0.f;
    unsigned out = half ? packbf(v0 - bfh(v0), v1 - bfh(v1))
                        : packbf(bfh(v0), bfh(v1));
    g_wp[idx] = __uint_as_float(out);
}

__global__ void k_setup(const float* __restrict__ h_in, const float* __restrict__ x_in,
                        const float* __restrict__ vel_in, const float* __restrict__ emb_w,
                        const float* __restrict__ emb_b) {
    int i = blockIdx.x * blockDim.x + threadIdx.x;
    if (i < NN * 3) { g_x[i] = x_in[i]; g_vel[i] = vel_in[i]; }
    if (i < NN) g_cnt[i] = 0.f;
    if (i < NN * HID) {
        int n = i >> 7, c = i & 127;
        float s = emb_b[c];
#pragma unroll
        for (int k = 0; k < 6; k++) s += h_in[n * 6 + k] * emb_w[k * HID + c];
        g_hA[i] = s;
    }
}

__global__ void k_count(const int* __restrict__ edges) {
    int e = blockIdx.x * blockDim.x + threadIdx.x;
    if (e < NE) atomicAdd(&g_cnt[edges[e]], 1.f);
}

__global__ void k_zero() {
    int i = blockIdx.x * blockDim.x + threadIdx.x;
    if (i < NN * 3) g_aggx[i] = 0.f;
    if (i < NN * HID) g_aggh[i] = 0.f;
}

// Fused edge kernel, bf16x3 mma.sync. 128 edges/CTA, grid 2500, 256 threads.
// Warps: eg = wid>>1 (32 edges), cg = wid&1 (64 cols). Warp tile 32x64.
__global__ void __launch_bounds__(256, 2) k_edge_mma(
    int cur, int layer, const float* __restrict__ ea, const int* __restrict__ edges,
    const float* __restrict__ eb1, const float* __restrict__ eb2,
    const float* __restrict__ aw, const float* __restrict__ ab,
    const float* __restrict__ cb1, const float* __restrict__ cw2) {
    extern __shared__ float sm[];
    float* sAfull = sm;           // 16384 floats: hi uint4[0,2048), mid [2048,4096)
    float* sBc = sm + 16384;      // 4096 floats: hi uint2[0,1024), mid [1024,2048)
    float* sEb1 = sm + 20480;
    float* sEb2 = sm + 20608;
    float* sAw = sm + 20736;
    float* sCb1 = sm + 20864;
    float* sCw2 = sm + 20992;
    float* sEa = sm + 21120;      // 256
    int* sRow = (int*)(sm + 21376);
    int* sCol = (int*)(sm + 21504);
    float* sCD = sm + 21632;      // 384
    float* sRad = sm + 22016;     // 128
    float* sGp = sm + 22144;      // 256
    float* sWv = sm + 22400;      // 128
    const float* hb = cur ? g_hB : g_hA;
    const float* wp1 = g_wp + layer * WP_L;
    const float* wp2 = wp1 + WP_EW2;
    const float* wp3 = wp1 + WP_CW1;
    const int tid = threadIdx.x, lane = tid & 31, wid = tid >> 5;
    const int eg = wid >> 1, cg = wid & 1;
    const int e0 = blockIdx.x * 128;
    uint4* aF = (uint4*)sAfull;

    if (tid < 128) {
        sEb1[tid] = eb1[tid]; sEb2[tid] = eb2[tid]; sAw[tid] = aw[tid];
        sCb1[tid] = cb1[tid]; sCw2[tid] = cw2[tid];
        int e = e0 + tid;
        int r = edges[e], c = edges[NE + e];
        sRow[tid] = r; sCol[tid] = c;
        float dx = g_x[r * 3] - g_x[c * 3];
        float dy = g_x[r * 3 + 1] - g_x[c * 3 + 1];
        float dz = g_x[r * 3 + 2] - g_x[c * 3 + 2];
        sCD[tid * 3] = dx; sCD[tid * 3 + 1] = dy; sCD[tid * 3 + 2] = dz;
        sRad[tid] = dx * dx + dy * dy + dz * dz;
    }
    sEa[tid] = ea[e0 * 2 + tid];
    float abv = ab[0];

    float acc[2][8][4];
#pragma unroll
    for (int m = 0; m < 2; m++)
#pragma unroll
        for (int t = 0; t < 8; t++)
#pragma unroll
            for (int i = 0; i < 4; i++) acc[m][t][i] = 0.f;

#define STAGE_B(wp, ci)                                                       \
    {                                                                         \
        const float4* srcB = (const float4*)((wp) + (ci) * 4096);             \
        float4* dstB = (float4*)sBc;                                          \
        _Pragma("unroll") for (int i = 0; i < 4; i++)                         \
            dstB[tid + 256 * i] = srcB[tid + 256 * i];                        \
    }
#define STAGE_A1(ci)                                                          \
    _Pragma("unroll") for (int s2 = 0; s2 < 2; s2++) {                        \
        int s = tid + 256 * s2;                                               \
        int ks = s >> 8, mt = (s >> 5) & 7, l = s & 31;                       \
        int r1 = 16 * mt + (l >> 2), r2 = r1 + 8;                             \
        float v10 = 0.f, v11 = 0.f, v12 = 0.f, v13 = 0.f;                     \
        float v20 = 0.f, v21 = 0.f, v22 = 0.f, v23 = 0.f;                     \
        if ((ci) < 8) {                                                       \
            const int* sI = ((ci) < 4) ? sRow : sCol;                         \
            int koff = 32 * ((ci) & 3) + 16 * ks + 2 * (l & 3);               \
            const float* p1 = hb + sI[r1] * HID + koff;                       \
            const float* p2 = hb + sI[r2] * HID + koff;                       \
            float2 x0 = *(const float2*)p1, x1 = *(const float2*)(p1 + 8);    \
            float2 y0 = *(const float2*)p2, y1 = *(const float2*)(p2 + 8);    \
            v10 = x0.x; v11 = x0.y; v12 = x1.x; v13 = x1.y;                   \
            v20 = y0.x; v21 = y0.y; v22 = y1.x; v23 = y1.y;                   \
        } else if (ks == 0) {                                                 \
            int kq = 2 * (l & 3);                                             \
            if (kq == 0) { v10 = sRad[r1]; v11 = sEa[2 * r1];                 \
                           v20 = sRad[r2]; v21 = sEa[2 * r2]; }               \
            else if (kq == 2) { v10 = sEa[2 * r1 + 1]; v20 = sEa[2 * r2 + 1]; } \
        }                                                                     \
        uint4 hi4 = make_uint4(packbf(bfh(v10), bfh(v11)),                    \
                               packbf(bfh(v20), bfh(v21)),                    \
                               packbf(bfh(v12), bfh(v13)),                    \
                               packbf(bfh(v22), bfh(v23)));                   \
        uint4 md4 = make_uint4(packbf(v10 - bfh(v10), v11 - bfh(v11)),        \
                               packbf(v20 - bfh(v20), v21 - bfh(v21)),        \
                               packbf(v12 - bfh(v12), v13 - bfh(v13)),        \
                               packbf(v22 - bfh(v22), v23 - bfh(v23)));       \
        aF[s] = hi4; aF[s + 512] = md4;                                       \
    }
#define MMA_CHUNK(midofs, kc0)                                                \
    _Pragma("unroll") for (int ks = 0; ks < 2; ks++) {                        \
        int ai = (((kc0) + ks) * 8 + 2 * eg) * 32 + lane;                     \
        uint4 ah0 = aF[ai], ah1 = aF[ai + 32];                                \
        uint4 am0 = aF[ai + (midofs)], am1 = aF[ai + 32 + (midofs)];          \
        _Pragma("unroll") for (int tl = 0; tl < 8; tl++) {                    \
            int bi = (ks * 16 + 8 * cg + tl) * 32 + lane;                     \
            uint2 bh = ((const uint2*)sBc)[bi];                               \
            uint2 bm = ((const uint2*)sBc)[bi + 1024];                        \
            mma16(acc[0][tl], ah0, bh); mma16(acc[0][tl], am0, bh);           \
            mma16(acc[0][tl], ah0, bm);                                       \
            mma16(acc[1][tl], ah1, bh); mma16(acc[1][tl], am1, bh);           \
            mma16(acc[1][tl], ah1, bm);                                       \
        }                                                                     \
    }
#define REPACK()                                                              \
    _Pragma("unroll") for (int kq = 0; kq < 4; kq++) {                        \
        int kc = 4 * cg + kq;                                                 \
        _Pragma("unroll") for (int mi = 0; mi < 2; mi++) {                    \
            float v0 = acc[mi][2 * kq][0], v1 = acc[mi][2 * kq][1];           \
            float v2 = acc[mi][2 * kq][2], v3 = acc[mi][2 * kq][3];           \
            float w0 = acc[mi][2 * kq + 1][0], w1 = acc[mi][2 * kq + 1][1];   \
            float w2 = acc[mi][2 * kq + 1][2], w3 = acc[mi][2 * kq + 1][3];   \
            uint4 hi4 = make_uint4(packbf(bfh(v0), bfh(v1)),                  \
                                   packbf(bfh(v2), bfh(v3)),                  \
                                   packbf(bfh(w0), bfh(w1)),                  \
                                   packbf(bfh(w2), bfh(w3)));                 \
            uint4 md4 = make_uint4(packbf(v0 - bfh(v0), v1 - bfh(v1)),        \
                                   packbf(v2 - bfh(v2), v3 - bfh(v3)),        \
                                   packbf(w0 - bfh(w0), w1 - bfh(w1)),        \
                                   packbf(w2 - bfh(w2), w3 - bfh(w3)));       \
            int o = (kc * 8 + 2 * eg + mi) * 32 + lane;                       \
            aF[o] = hi4; aF[o + 2048] = md4;                                  \
        }                                                                     \
    }
#define ZACC()                                                                \
    _Pragma("unroll") for (int m = 0; m < 2; m++)                             \
        _Pragma("unroll") for (int t = 0; t < 8; t++)                         \
            _Pragma("unroll") for (int i = 0; i < 4; i++) acc[m][t][i] = 0.f;

    // ---- GEMM1: t1 = e_in @ ew1 (K=259 -> 9 chunks of 32) ----
    for (int ci = 0; ci < 9; ci++) {
        __syncthreads();
        STAGE_A1(ci);
        STAGE_B(wp1, ci);
        __syncthreads();
        MMA_CHUNK(512, 0);
    }
    __syncthreads();
    // epilogue1: silu(+eb1) -> bf16 hi/mid A-fragments (same-lane repack)
#pragma unroll
    for (int mi = 0; mi < 2; mi++)
#pragma unroll
        for (int t = 0; t < 8; t++) {
            int c0 = 64 * cg + 8 * t + 2 * (lane & 3);
            float b0 = sEb1[c0], b1 = sEb1[c0 + 1];
            acc[mi][t][0] = siluf(acc[mi][t][0] + b0);
            acc[mi][t][1] = siluf(acc[mi][t][1] + b1);
            acc[mi][t][2] = siluf(acc[mi][t][2] + b0);
            acc[mi][t][3] = siluf(acc[mi][t][3] + b1);
        }
    REPACK();
    ZACC();

    // ---- GEMM2: m_raw = t1 @ ew2 (4 chunks) ----
    for (int ci = 0; ci < 4; ci++) {
        __syncthreads();
        STAGE_B(wp2, ci);
        __syncthreads();
        MMA_CHUNK(2048, 2 * ci);
    }
    // epilogue2: m = silu(+eb2); gate; scale; agg_h red2; repack
    {
        float p[2][2] = {{0.f, 0.f}, {0.f, 0.f}};
#pragma unroll
        for (int mi = 0; mi < 2; mi++)
#pragma unroll
            for (int t = 0; t < 8; t++) {
                int c0 = 64 * cg + 8 * t + 2 * (lane & 3);
                float b0 = sEb2[c0], b1 = sEb2[c0 + 1];
                float w0 = sAw[c0], w1 = sAw[c0 + 1];
                acc[mi][t][0] = siluf(acc[mi][t][0] + b0);
                acc[mi][t][1] = siluf(acc[mi][t][1] + b1);
                acc[mi][t][2] = siluf(acc[mi][t][2] + b0);
                acc[mi][t][3] = siluf(acc[mi][t][3] + b1);
                p[mi][0] += acc[mi][t][0] * w0 + acc[mi][t][1] * w1;
                p[mi][1] += acc[mi][t][2] * w0 + acc[mi][t][3] * w1;
            }
#pragma unroll
        for (int mi = 0; mi < 2; mi++)
#pragma unroll
            for (int h = 0; h < 2; h++) {
                float v = p[mi][h];
                v += __shfl_xor_sync(0xffffffffu, v, 1);
                v += __shfl_xor_sync(0xffffffffu, v, 2);
                p[mi][h] = v;
            }
        if ((lane & 3) == 0) {
#pragma unroll
            for (int mi = 0; mi < 2; mi++) {
                int e = 32 * eg + 16 * mi + (lane >> 2);
                sGp[cg * 128 + e] = p[mi][0];
                sGp[cg * 128 + e + 8] = p[mi][1];
            }
        }
        __syncthreads();
#pragma unroll
        for (int mi = 0; mi < 2; mi++) {
            int e = 32 * eg + 16 * mi + (lane >> 2);
            float g0 = sigf(sGp[e] + sGp[128 + e] + abv);
            float g1 = sigf(sGp[e + 8] + sGp[128 + e + 8] + abv);
            int n1 = sRow[e] * HID, n2 = sRow[e + 8] * HID;
#pragma unroll
            for (int t = 0; t < 8; t++) {
                int c0 = 64 * cg + 8 * t + 2 * (lane & 3);
                acc[mi][t][0] *= g0; acc[mi][t][1] *= g0;
                acc[mi][t][2] *= g1; acc[mi][t][3] *= g1;
                red2(&g_aggh[n1 + c0], acc[mi][t][0], acc[mi][t][1]);
                red2(&g_aggh[n2 + c0], acc[mi][t][2], acc[mi][t][3]);
            }
        }
        REPACK();
        ZACC();
    }

    // ---- GEMM3: t3_raw = m @ cw1 (4 chunks) ----
    for (int ci = 0; ci < 4; ci++) {
        __syncthreads();
        STAGE_B(wp3, ci);
        __syncthreads();
        MMA_CHUNK(2048, 2 * ci);
    }
    // epilogue3: w = silu(+cb1) . cw2 ; agg_x
    {
        float p[2][2] = {{0.f, 0.f}, {0.f, 0.f}};
#pragma unroll
        for (int mi = 0; mi < 2; mi++)
#pragma unroll
            for (int t = 0; t < 8; t++) {
                int c0 = 64 * cg + 8 * t + 2 * (lane & 3);
                float b0 = sCb1[c0], b1 = sCb1[c0 + 1];
                float w0 = sCw2[c0], w1 = sCw2[c0 + 1];
                p[mi][0] += siluf(acc[mi][t][0] + b0) * w0
                          + siluf(acc[mi][t][1] + b1) * w1;
                p[mi][1] += siluf(acc[mi][t][2] + b0) * w0
                          + siluf(acc[mi][t][3] + b1) * w1;
            }
#pragma unroll
        for (int mi = 0; mi < 2; mi++)
#pragma unroll
            for (int h = 0; h < 2; h++) {
                float v = p[mi][h];
                v += __shfl_xor_sync(0xffffffffu, v, 1);
                v += __shfl_xor_sync(0xffffffffu, v, 2);
                p[mi][h] = v;
            }
        __syncthreads();
        if ((lane & 3) == 0) {
#pragma unroll
            for (int mi = 0; mi < 2; mi++) {
                int e = 32 * eg + 16 * mi + (lane >> 2);
                sGp[cg * 128 + e] = p[mi][0];
                sGp[cg * 128 + e + 8] = p[mi][1];
            }
        }
    }
    __syncthreads();
    if (tid < 128) sWv[tid] = sGp[tid] + sGp[128 + tid];
    __syncthreads();
    for (int i = tid; i < 384; i += 256) {
        int e = i / 3, d = i - e * 3;
        atomicAdd(&g_aggx[sRow[e] * 3 + d], sCD[i] * sWv[e]);
    }
#undef STAGE_B
#undef STAGE_A1
#undef MMA_CHUNK
#undef REPACK
#undef ZACC
}

// ---------------- scalar node kernel (proven R9 path) ----------------
__device__ __forceinline__ void gemm64(const float* sA, float* sW,
                                       const float* __restrict__ gW,
                                       int K, int Kpad, float acc[8][4]) {
    const int tid = threadIdx.x, tx = tid & 31, ty = tid >> 5;
    unsigned long long a2[4][4];
#pragma unroll
    for (int p = 0; p < 4; p++)
#pragma unroll
        for (int j = 0; j < 4; j++) a2[p][j] = 0ULL;
    const float4* __restrict__ gW4 = (const float4*)gW;
    const int nch = Kpad >> 5;
    float4 r[4];
#pragma unroll
    for (int i = 0; i < 4; i++) {
        int f = tid + i * 256;
        int rr = f >> 5;
        r[i] = (rr < K) ? gW4[rr * 32 + (f & 31)] : make_float4(0.f, 0.f, 0.f, 0.f);
    }
#pragma unroll
    for (int i = 0; i < 4; i++) ((float4*)sW)[tid + i * 256] = r[i];
    for (int ci = 0; ci < nch; ci++) {
        __syncthreads();
        const int kb = ci << 5;
        const float* buf = sW + ((ci & 1) << 12);
        const bool more = (ci + 1 < nch);
        if (more) {
#pragma unroll
            for (int i = 0; i < 4; i++) {
                int f = tid + i * 256;
                int rr = kb + 32 + (f >> 5);
                r[i] = (rr < K) ? gW4[rr * 32 + (f & 31)]
                                : make_float4(0.f, 0.f, 0.f, 0.f);
            }
        }
#pragma unroll 8
        for (int kk = 0; kk < 32; kk++) {
            int k = kb + kk;
            int rot = ((k >> 2) & 15) << 2;
            const float* ar = sA + k * 64;
            ulonglong2 a0 = *(const ulonglong2*)(ar + ((8 * ty + rot) & 63));
            ulonglong2 a1 = *(const ulonglong2*)(ar + ((8 * ty + 4 + rot) & 63));
            float4 w = *(const float4*)(buf + kk * 128 + 4 * tx);
            unsigned long long w0 = pack2(w.x), w1 = pack2(w.y);
            unsigned long long w2 = pack2(w.z), w3 = pack2(w.w);
            ffma2(a2[0][0], a0.x, w0); ffma2(a2[0][1], a0.x, w1);
            ffma2(a2[0][2], a0.x, w2); ffma2(a2[0][3], a0.x, w3);
            ffma2(a2[1][0], a0.y, w0); ffma2(a2[1][1], a0.y, w1);
            ffma2(a2[1][2], a0.y, w2); ffma2(a2[1][3], a0.y, w3);
            ffma2(a2[2][0], a1.x, w0); ffma2(a2[2][1], a1.x, w1);
            ffma2(a2[2][2], a1.x, w2); ffma2(a2[2][3], a1.x, w3);
            ffma2(a2[3][0], a1.y, w0); ffma2(a2[3][1], a1.y, w1);
            ffma2(a2[3][2], a1.y, w2); ffma2(a2[3][3], a1.y, w3);
        }
        if (more) {
            float* nb = sW + (((ci + 1) & 1) << 12);
#pragma unroll
            for (int i = 0; i < 4; i++) ((float4*)nb)[tid + i * 256] = r[i];
        }
    }
#pragma unroll
    for (int p = 0; p < 4; p++)
#pragma unroll
        for (int j = 0; j < 4; j++) unpack2(a2[p][j], acc[2 * p][j], acc[2 * p + 1][j]);
    __syncthreads();
}

__device__ __forceinline__ void store_out64(float* sA, int baseRow, float acc[8][4],
                                            const float* __restrict__ bias) {
    const int tid = threadIdx.x, tx = tid & 31, ty = tid >> 5;
#pragma unroll
    for (int j = 0; j < 4; j++) {
        int c = 4 * tx + j;
        float b = bias[c];
        int rot = ((c >> 2) & 15) << 2;
        float* rp = sA + (baseRow + c) * 64;
        float4 v0, v1;
        v0.x = siluf(acc[0][j] + b); v0.y = siluf(acc[1][j] + b);
        v0.z = siluf(acc[2][j] + b); v0.w = siluf(acc[3][j] + b);
        v1.x = siluf(acc[4][j] + b); v1.y = siluf(acc[5][j] + b);
        v1.z = siluf(acc[6][j] + b); v1.w = siluf(acc[7][j] + b);
        *(float4*)(rp + ((8 * ty + rot) & 63)) = v0;
        *(float4*)(rp + ((8 * ty + 4 + rot) & 63)) = v1;
    }
}

__global__ void __launch_bounds__(256, 2) k_node(
    int cur, const float* __restrict__ nw1, const float* __restrict__ nb1,
    const float* __restrict__ nw2, const float* __restrict__ nb2,
    const float* __restrict__ vw1, const float* __restrict__ vb1,
    const float* __restrict__ vw2, const float* __restrict__ vb2) {
    extern __shared__ float sm[];
    float* sA = sm;
    float* sW = sm + 16384;
    float* sS = sm + 24576;
    float* sVw2 = sm + 24640;
    const float* hb = cur ? g_hB : g_hA;
    float* hn = cur ? g_hA : g_hB;
    const int tid = threadIdx.x, tx = tid & 31, ty = tid >> 5;
    const int n0 = blockIdx.x * 64;

    if (tid < 128) sVw2[tid] = vw2[tid];
    for (int it = tid; it < 2048; it += 256) {
        int e = it & 63, q = it >> 6;
        int n = n0 + e;
        float4 v = (n < NN) ? *(const float4*)(hb + n * HID + 4 * q)
                            : make_float4(0.f, 0.f, 0.f, 0.f);
        float4 a = (n < NN) ? *(const float4*)(g_aggh + n * HID + 4 * q)
                            : make_float4(0.f, 0.f, 0.f, 0.f);
        int p = (e + ((q & 15) << 2)) & 63;
        int kb = 4 * q * 64;
        sA[kb + p] = v.x; sA[kb + 64 + p] = v.y;
        sA[kb + 128 + p] = v.z; sA[kb + 192 + p] = v.w;
        int kb2 = (128 + 4 * q) * 64;
        sA[kb2 + p] = a.x; sA[kb2 + 64 + p] = a.y;
        sA[kb2 + 128 + p] = a.z; sA[kb2 + 192 + p] = a.w;
    }

    float acc[8][4];
    gemm64(sA, sW, vw1, 128, 128, acc);
    {
        float sp[8] = {0, 0, 0, 0, 0, 0, 0, 0};
#pragma unroll
        for (int j = 0; j < 4; j++) {
            int c = 4 * tx + j;
            float b = vb1[c], w2 = sVw2[c];
#pragma unroll
            for (int e = 0; e < 8; e++) sp[e] += siluf(acc[e][j] + b) * w2;
        }
        float vb2s = vb2[0];
#pragma unroll
        for (int e = 0; e < 8; e++) {
            float v = sp[e];
            v += __shfl_xor_sync(0xffffffffu, v, 16);
            v += __shfl_xor_sync(0xffffffffu, v, 8);
            v += __shfl_xor_sync(0xffffffffu, v, 4);
            v += __shfl_xor_sync(0xffffffffu, v, 2);
            v += __shfl_xor_sync(0xffffffffu, v, 1);
            if (tx == 0) sS[8 * ty + e] = v + vb2s;
        }
    }
    __syncthreads();
    if (tid < 64) {
        int n = n0 + tid;
        if (n < NN) {
            float cnt = fmaxf(g_cnt[n], 1.f);
            float s = sS[tid];
#pragma unroll
            for (int d = 0; d < 3; d++) {
                float vn = s * g_vel[n * 3 + d];
                g_vel[n * 3 + d] = vn;
                g_x[n * 3 + d] += g_aggx[n * 3 + d] / cnt + vn;
            }
        }
    }
    gemm64(sA, sW, nw1, 256, 256, acc);
    store_out64(sA, 0, acc, nb1);
    gemm64(sA, sW, nw2, 128, 128, acc);
#pragma unroll
    for (int e = 0; e < 8; e++) {
        int n = n0 + 8 * ty + e;
        if (n < NN) {
            float4 v;
            v.x = acc[e][0] + nb2[4 * tx];
            v.y = acc[e][1] + nb2[4 * tx + 1];
            v.z = acc[e][2] + nb2[4 * tx + 2];
            v.w = acc[e][3] + nb2[4 * tx + 3];
            *(float4*)(hn + n * HID + 4 * tx) = v;
        }
    }
}

__global__ void k_proj(const float* __restrict__ pw, const float* __restrict__ pb,
                       float* __restrict__ out) {
    int i = blockIdx.x * blockDim.x + threadIdx.x;
    if (i < NN * 3) {
        int n = i / 3, p = i - n * 3;
        float s = pb[p];
        const float* hr = g_hA + n * HID;
#pragma unroll 16
        for (int k = 0; k < HID; k++) s += hr[k] * pw[k * 3 + p];
        out[i] = s;
    } else if (i < NN * 6) {
        out[i] = g_x[i - NN * 3];
    } else if (i < NN * 9) {
        out[i] = g_vel[i - NN * 6];
    }
}

extern "C" void kernel_launch(void* const* d_in, const int* in_sizes, int n_in,
                              void* d_out, int out_size) {
    const float* h_in = (const float*)d_in[0];
    const float* x_in = (const float*)d_in[1];
    const float* vel_in = (const float*)d_in[2];
    const float* ea = (const float*)d_in[3];
    const int* edges = (const int*)d_in[4];
    const float* emb_w = (const float*)d_in[5];
    const float* emb_b = (const float*)d_in[6];
    const float* ew1 = (const float*)d_in[7];
    const float* eb1 = (const float*)d_in[8];
    const float* ew2 = (const float*)d_in[9];
    const float* eb2 = (const float*)d_in[10];
    const float* aw = (const float*)d_in[11];
    const float* ab = (const float*)d_in[12];
    const float* nw1 = (const float*)d_in[13];
    const float* nb1 = (const float*)d_in[14];
    const float* nw2 = (const float*)d_in[15];
    const float* nb2 = (const float*)d_in[16];
    const float* cw1 = (const float*)d_in[17];
    const float* cb1 = (const float*)d_in[18];
    const float* cw2 = (const float*)d_in[19];
    const float* vw1 = (const float*)d_in[20];
    const float* vb1 = (const float*)d_in[21];
    const float* vw2 = (const float*)d_in[22];
    const float* vb2 = (const float*)d_in[23];
    const float* pw = (const float*)d_in[24];
    const float* pb = (const float*)d_in[25];

    const int SMN = SMN_FLOATS * 4;
    cudaFuncSetAttribute(k_edge_mma, cudaFuncAttributeMaxDynamicSharedMemorySize, SME_BYTES);
    cudaFuncSetAttribute(k_node, cudaFuncAttributeMaxDynamicSharedMemorySize, SMN);

    k_setup<<<5000, 256>>>(h_in, x_in, vel_in, emb_w, emb_b);
    k_count<<<1250, 256>>>(edges);
    k_permw<<<1088, 256>>>(ew1, ew2, cw1);
    for (int i = 0; i < 4; i++) {
        k_zero<<<5000, 256>>>();
        k_edge_mma<<<2500, 256, SME_BYTES>>>(i & 1, i, ea, edges,
            eb1 + i * HID, eb2 + i * HID, aw + i * HID, ab + i,
            cb1 + i * HID, cw2 + i * HID);
        k_node<<<157, 256, SMN>>>(i & 1,
            nw1 + i * 256 * HID, nb1 + i * HID,
            nw2 + i * HID * HID, nb2 + i * HID,
            vw1 + i * HID * HID, vb1 + i * HID,
            vw2 + i * HID, vb2 + i);
    }
    k_proj<<<(NN * 9 + 255) / 256, 256>>>(pw, pb, (float*)d_out);
}